// round 9
// baseline (speedup 1.0000x reference)
#include <cuda_runtime.h>
#include <cuda_bf16.h>
#include <cstdint>

#define N_DIM   16384
#define F_DIM   32
#define BM      256
#define BK      32
#define THREADS 256
#define GRID    148
#define KCHUNKS 16
#define UNIT_STAGES 32                     // 32 stages x BK=32 -> 1024 k per unit
#define TOTAL_UNITS (64 * KCHUNKS)         // 64 m-tiles x 16 k-chunks = 1024
#define ROWB    80                         // B bf16 smem row stride (64B + 16 pad)

// ---- smem stage layout ----
#define STAGE_A_SZ 32768                   // 256 rows x 32 f32 (128B/row, swizzled)
#define BH_SZ      2560                    // 32 rows x 80B
#define STAGE_SZ   (STAGE_A_SZ + 2 * BH_SZ)   // 37888
#define NSTAGE     5
#define SMEM_TOTAL (NSTAGE * STAGE_SZ)     // 189440 (1 CTA/SM)

__device__ __align__(16) __nv_bfloat16 g_bh1[F_DIM * N_DIM];
__device__ __align__(16) __nv_bfloat16 g_bl1[F_DIM * N_DIM];
__device__ __align__(16) __nv_bfloat16 g_bh2[F_DIM * N_DIM];
__device__ __align__(16) __nv_bfloat16 g_bl2[F_DIM * N_DIM];
__device__ __align__(16) float g_part[KCHUNKS * N_DIM * F_DIM];   // 32 MB

// ---------------- helpers ----------------
__device__ __forceinline__ uint32_t smem_u32(const void* p) {
    uint32_t a;
    asm("{ .reg .u64 t; cvta.to.shared.u64 t, %1; cvt.u32.u64 %0, t; }" : "=r"(a) : "l"(p));
    return a;
}
#define CP_ASYNC16(dst, src) \
    asm volatile("cp.async.cg.shared.global [%0], [%1], 16;" :: "r"(dst), "l"(src) : "memory")
#define CP_COMMIT()  asm volatile("cp.async.commit_group;" ::: "memory")
#define CP_WAIT3()   asm volatile("cp.async.wait_group 3;" ::: "memory")

__device__ __forceinline__ float2 lds_f2(uint32_t a) {
    float2 v;
    asm volatile("ld.shared.v2.f32 {%0,%1}, [%2];" : "=f"(v.x), "=f"(v.y) : "r"(a));
    return v;
}
__device__ __forceinline__ uint32_t lds32(uint32_t addr) {
    uint32_t v;
    asm volatile("ld.shared.b32 %0, [%1];" : "=r"(v) : "r"(addr));
    return v;
}
__device__ __forceinline__ void mma_bf16(float* c, const uint32_t* a, uint32_t b0, uint32_t b1) {
    asm volatile("mma.sync.aligned.m16n8k16.row.col.f32.bf16.bf16.f32 "
                 "{%0,%1,%2,%3}, {%4,%5,%6,%7}, {%8,%9}, {%0,%1,%2,%3};"
                 : "+f"(c[0]), "+f"(c[1]), "+f"(c[2]), "+f"(c[3])
                 : "r"(a[0]), "r"(a[1]), "r"(a[2]), "r"(a[3]), "r"(b0), "r"(b1));
}
__device__ __forceinline__ uint32_t pack_bf16_rn(float lo, float hi) {
    uint32_t r;
    asm("cvt.rn.bf16x2.f32 %0, %1, %2;" : "=r"(r) : "f"(hi), "f"(lo));
    return r;
}
__device__ __forceinline__ uint32_t split2(float2 v, uint32_t& lo) {
    uint32_t hx = (__float_as_uint(v.x) + 0x8000u) & 0xFFFF0000u;
    uint32_t hy = (__float_as_uint(v.y) + 0x8000u) & 0xFFFF0000u;
    lo = pack_bf16_rn(v.x - __uint_as_float(hx), v.y - __uint_as_float(hy));
    return __byte_perm(hx, hy, 0x7632);
}
__device__ __forceinline__ void split_g(float v, __nv_bfloat16* ph, __nv_bfloat16* pl) {
    __nv_bfloat16 h = __float2bfloat16(v);
    *ph = h;
    *pl = __float2bfloat16(v - __bfloat162float(h));
}

// ---------- prep: split((features @ W)^T) -> g_bh1/g_bl1 (2 threads per row) ----------
__global__ void feat_w_kernel(const float* __restrict__ feat,
                              const float* __restrict__ W) {
    __shared__ float sW[F_DIM * F_DIM];
    int tid = threadIdx.x;
    for (int i = tid; i < F_DIM * F_DIM; i += 128) sW[i] = W[i];
    __syncthreads();
    int g = blockIdx.x * 128 + tid;
    int row = g >> 1;
    int c0  = (g & 1) * 16;
    float f[F_DIM];
    const float4* fr = reinterpret_cast<const float4*>(feat + (size_t)row * F_DIM);
#pragma unroll
    for (int i = 0; i < 8; i++) {
        float4 v = fr[i];
        f[4*i] = v.x; f[4*i+1] = v.y; f[4*i+2] = v.z; f[4*i+3] = v.w;
    }
#pragma unroll 4
    for (int cc = 0; cc < 16; cc++) {
        int c = c0 + cc;
        float acc = 0.f;
#pragma unroll
        for (int k = 0; k < F_DIM; k++) acc = fmaf(f[k], sW[k * F_DIM + c], acc);
        split_g(acc, &g_bh1[(size_t)c * N_DIM + row], &g_bl1[(size_t)c * N_DIM + row]);
    }
}

// ---------- persistent big GEMM: BM=256, partials over K-chunks ----------
template <int MODE>
__global__ __launch_bounds__(THREADS, 1)
void big_gemm_mma(const float* __restrict__ A) {
    const __nv_bfloat16* __restrict__ Bh = (MODE == 1) ? g_bh1 : g_bh2;
    const __nv_bfloat16* __restrict__ Bl = (MODE == 1) ? g_bl1 : g_bl2;

    extern __shared__ char smem[];
    const uint32_t sb = smem_u32(smem);
    const int tid  = threadIdx.x;
    const int lane = tid & 31;
    const int w    = tid >> 5;           // warp w -> rows w*32 .. w*32+31

    const int u0 = (blockIdx.x * TOTAL_UNITS) / GRID;
    const int u1 = ((blockIdx.x + 1) * TOTAL_UNITS) / GRID;
    const int S0 = u0 * UNIT_STAGES;
    const int S1 = u1 * UNIT_STAGES;

    // ---- producer slots ----
    // A: 256 rows x 8 granules(16B) = 2048 chunks -> 8 per thread
    int arow[8]; int agr[8]; uint32_t adst[8];
#pragma unroll
    for (int i = 0; i < 8; i++) {
        int chunk = tid + THREADS * i;
        arow[i] = chunk >> 3;  agr[i] = chunk & 7;
        adst[i] = (uint32_t)(arow[i] * 128 + ((agr[i] ^ (arow[i] & 7)) << 4));
    }
    // B: 32n x 4 granules, h & l -> 256 chunks -> 1 per thread
    const int bn = (tid & 127) >> 2, bg = (tid & 127) & 3;
    const __nv_bfloat16* bsrc = ((tid < 128) ? Bh : Bl) + (size_t)bn * N_DIM + bg * 8;
    const uint32_t bdst = (uint32_t)(STAGE_A_SZ + ((tid < 128) ? 0 : BH_SZ) + bn * ROWB + bg * 16);

    auto issue = [&](int s) {
        const int u = s >> 5;
        const int m = u >> 4;
        const int kf = ((u & 15) * UNIT_STAGES + (s & 31)) * BK;
        const uint32_t stg = sb + (uint32_t)(s % NSTAGE) * STAGE_SZ;
        const float* abase = A + (size_t)(m * BM) * N_DIM + kf;
#pragma unroll
        for (int i = 0; i < 8; i++)
            CP_ASYNC16(stg + adst[i], abase + (size_t)arow[i] * N_DIM + agr[i] * 4);
        CP_ASYNC16(stg + bdst, bsrc + kf);
    };

    // ---- consumer addressing ----
    const int rA = w * 32 + (lane >> 2);            // tile0 frag row; tiles at +0,+8,+16,+24
    const uint32_t xr = (uint32_t)(rA & 7);         // same for +8/+16/+24
    const uint32_t ar0 = (uint32_t)(rA * 128);
    const uint32_t gb  = (uint32_t)((lane & 3) >> 1);
    const uint32_t aib = (uint32_t)((lane & 1) * 8);
    const uint32_t boff = (uint32_t)(STAGE_A_SZ + (lane >> 2) * ROWB + (lane & 3) * 4);

    float acc[2][4][4];
#pragma unroll
    for (int t = 0; t < 2; t++)
#pragma unroll
        for (int j = 0; j < 4; j++)
#pragma unroll
            for (int i = 0; i < 4; i++) acc[t][j][i] = 0.f;

    issue(S0);     CP_COMMIT();
    issue(S0 + 1); CP_COMMIT();
    issue(S0 + 2); CP_COMMIT();
    issue(S0 + 3); CP_COMMIT();

    for (int s = S0; s < S1; s++) {
        CP_WAIT3();
        __syncthreads();
        if (s + 4 < S1) issue(s + 4);
        CP_COMMIT();

        const uint32_t stg = sb + (uint32_t)(s % NSTAGE) * STAGE_SZ;
#pragma unroll
        for (int kk = 0; kk < 2; kk++) {
            const uint32_t g0 = (gb + (uint32_t)(kk * 4)) ^ xr;
            const uint32_t g2 = (gb + (uint32_t)(kk * 4) + 2) ^ xr;
            uint32_t ah[2][4], al[2][4];
#pragma unroll
            for (int t = 0; t < 2; t++) {
                const uint32_t r0b = stg + ar0 + (uint32_t)(t * 16 * 128);
                float2 v0 = lds_f2(r0b + (g0 << 4) + aib);
                float2 v1 = lds_f2(r0b + 8 * 128 + (g0 << 4) + aib);
                float2 v2 = lds_f2(r0b + (g2 << 4) + aib);
                float2 v3 = lds_f2(r0b + 8 * 128 + (g2 << 4) + aib);
                ah[t][0] = split2(v0, al[t][0]);
                ah[t][1] = split2(v1, al[t][1]);
                ah[t][2] = split2(v2, al[t][2]);
                ah[t][3] = split2(v3, al[t][3]);
            }
            const uint32_t bH = stg + boff + (uint32_t)(kk * 32);
#pragma unroll
            for (int j = 0; j < 4; j++) {
                const uint32_t bo = bH + (uint32_t)(j * 8 * ROWB);
                uint32_t bh0 = lds32(bo);
                uint32_t bh1 = lds32(bo + 16);
                uint32_t bl0 = lds32(bo + BH_SZ);
                uint32_t bl1 = lds32(bo + BH_SZ + 16);
#pragma unroll
                for (int t = 0; t < 2; t++) {
                    mma_bf16(acc[t][j], ah[t], bh0, bh1);
                    mma_bf16(acc[t][j], al[t], bh0, bh1);
                    mma_bf16(acc[t][j], ah[t], bl0, bl1);
                }
            }
        }

        if ((s & 31) == 31) {          // unit complete -> flush partials
            const int u = s >> 5;
            const int m = u >> 4, kc = u & 15;
            float* pp = g_part + ((size_t)kc << 19);
#pragma unroll
            for (int t = 0; t < 2; t++) {
                const int gr0 = m * BM + w * 32 + t * 16 + (lane >> 2);
                const int gr1 = gr0 + 8;
#pragma unroll
                for (int j = 0; j < 4; j++) {
                    const int c = j * 8 + (lane & 3) * 2;
                    *reinterpret_cast<float2*>(pp + (size_t)gr0 * F_DIM + c) =
                        make_float2(acc[t][j][0], acc[t][j][1]);
                    *reinterpret_cast<float2*>(pp + (size_t)gr1 * F_DIM + c) =
                        make_float2(acc[t][j][2], acc[t][j][3]);
                    acc[t][j][0] = acc[t][j][1] = acc[t][j][2] = acc[t][j][3] = 0.f;
                }
            }
        }
    }
}

// ---------- reduce partials -> diag scale -> split -> g_bh2/g_bl2 (transposed) ----------
__global__ void reduce_split_kernel(const float* __restrict__ diag) {
    __shared__ unsigned short sh[F_DIM][33], sl[F_DIM][33];
    const int tid = threadIdx.x;
    const int r0 = blockIdx.x * 32;
    const int rl = tid >> 3;
    const int c4 = (tid & 7) * 4;
    const int r = r0 + rl;
    float4 acc = *reinterpret_cast<const float4*>(g_part + (size_t)r * F_DIM + c4);
#pragma unroll
    for (int kc = 1; kc < KCHUNKS; kc++) {
        float4 v = *reinterpret_cast<const float4*>(
            g_part + ((size_t)kc << 19) + (size_t)r * F_DIM + c4);
        acc.x += v.x; acc.y += v.y; acc.z += v.z; acc.w += v.w;
    }
    const float d = diag[r];
    float vv[4] = {acc.x * d, acc.y * d, acc.z * d, acc.w * d};
#pragma unroll
    for (int i = 0; i < 4; i++) {
        __nv_bfloat16 h = __float2bfloat16(vv[i]);
        __nv_bfloat16 l = __float2bfloat16(vv[i] - __bfloat162float(h));
        sh[c4 + i][rl] = __bfloat16_as_ushort(h);
        sl[c4 + i][rl] = __bfloat16_as_ushort(l);
    }
    __syncthreads();
    const int cc = tid >> 3;
    const int rr = (tid & 7) * 4;
    ushort4 oh = make_ushort4(sh[cc][rr], sh[cc][rr+1], sh[cc][rr+2], sh[cc][rr+3]);
    ushort4 ol = make_ushort4(sl[cc][rr], sl[cc][rr+1], sl[cc][rr+2], sl[cc][rr+3]);
    *reinterpret_cast<ushort4*>(&g_bh2[(size_t)cc * N_DIM + r0 + rr]) = oh;
    *reinterpret_cast<ushort4*>(&g_bl2[(size_t)cc * N_DIM + r0 + rr]) = ol;
}

// ---------- reduce partials -> f32 out ----------
__global__ void reduce_out_kernel(float* __restrict__ out) {
    const int idx = blockIdx.x * blockDim.x + threadIdx.x;
    float4 acc = *reinterpret_cast<const float4*>(g_part + (size_t)idx * 4);
#pragma unroll
    for (int kc = 1; kc < KCHUNKS; kc++) {
        float4 v = *reinterpret_cast<const float4*>(
            g_part + ((size_t)kc << 19) + (size_t)idx * 4);
        acc.x += v.x; acc.y += v.y; acc.z += v.z; acc.w += v.w;
    }
    *reinterpret_cast<float4*>(out + (size_t)idx * 4) = acc;
}

extern "C" void kernel_launch(void* const* d_in, const int* in_sizes, int n_in,
                              void* d_out, int out_size) {
    const float* feat = (const float*)d_in[0];  // [16384, 32]
    const float* wav  = (const float*)d_in[1];  // [16384, 16384]
    const float* wavi = (const float*)d_in[2];  // [16384, 16384]
    const float* diag = (const float*)d_in[3];  // [16384]
    const float* Wm   = (const float*)d_in[4];  // [32, 32]
    float* out = (float*)d_out;

    cudaFuncSetAttribute(big_gemm_mma<1>, cudaFuncAttributeMaxDynamicSharedMemorySize, SMEM_TOTAL);
    cudaFuncSetAttribute(big_gemm_mma<2>, cudaFuncAttributeMaxDynamicSharedMemorySize, SMEM_TOTAL);

    feat_w_kernel<<<N_DIM * 2 / 128, 128>>>(feat, Wm);
    big_gemm_mma<1><<<GRID, THREADS, SMEM_TOTAL>>>(wavi);
    reduce_split_kernel<<<N_DIM / 32, 256>>>(diag);
    big_gemm_mma<2><<<GRID, THREADS, SMEM_TOTAL>>>(wav);
    reduce_out_kernel<<<(N_DIM * F_DIM / 4) / 256, 256>>>(out);
}

// round 10
// speedup vs baseline: 1.0528x; 1.0528x over previous
#include <cuda_runtime.h>
#include <cuda_fp16.h>
#include <cstdint>

#define N_DIM   16384
#define F_DIM   32
#define BM      256
#define BK      32
#define THREADS 256
#define GRID    148
#define KCHUNKS 16
#define UNIT_STAGES 32
#define TOTAL_UNITS (64 * KCHUNKS)         // 1024
#define ROWB    80                         // B fp16 smem row stride (64B + 16 pad)

// ---- smem stage layout ----
#define STAGE_A_SZ 32768                   // 256 rows x 32 f32 (128B/row, swizzled)
#define BH_SZ      2560                    // 32 rows x 80B  (single fp16 B)
#define STAGE_SZ   (STAGE_A_SZ + BH_SZ)    // 35328
#define NSTAGE     5
#define SMEM_TOTAL (NSTAGE * STAGE_SZ)     // 176640 (1 CTA/SM)

__device__ __align__(16) __half g_b1[F_DIM * N_DIM];   // (features@W)^T fp16
__device__ __align__(16) __half g_b2[F_DIM * N_DIM];   // (diag*(Winv@x))^T fp16
__device__ __align__(16) float g_part[KCHUNKS * N_DIM * F_DIM];

// ---------------- helpers ----------------
__device__ __forceinline__ uint32_t smem_u32(const void* p) {
    uint32_t a;
    asm("{ .reg .u64 t; cvta.to.shared.u64 t, %1; cvt.u32.u64 %0, t; }" : "=r"(a) : "l"(p));
    return a;
}
#define CP_ASYNC16(dst, src) \
    asm volatile("cp.async.cg.shared.global [%0], [%1], 16;" :: "r"(dst), "l"(src) : "memory")
#define CP_COMMIT()  asm volatile("cp.async.commit_group;" ::: "memory")
#define CP_WAIT3()   asm volatile("cp.async.wait_group 3;" ::: "memory")

__device__ __forceinline__ float2 lds_f2(uint32_t a) {
    float2 v;
    asm volatile("ld.shared.v2.f32 {%0,%1}, [%2];" : "=f"(v.x), "=f"(v.y) : "r"(a));
    return v;
}
__device__ __forceinline__ uint32_t lds32(uint32_t addr) {
    uint32_t v;
    asm volatile("ld.shared.b32 %0, [%1];" : "=r"(v) : "r"(addr));
    return v;
}
__device__ __forceinline__ void mma_f16(float* c, const uint32_t* a, uint32_t b0, uint32_t b1) {
    asm volatile("mma.sync.aligned.m16n8k16.row.col.f32.f16.f16.f32 "
                 "{%0,%1,%2,%3}, {%4,%5,%6,%7}, {%8,%9}, {%0,%1,%2,%3};"
                 : "+f"(c[0]), "+f"(c[1]), "+f"(c[2]), "+f"(c[3])
                 : "r"(a[0]), "r"(a[1]), "r"(a[2]), "r"(a[3]), "r"(b0), "r"(b1));
}
// split f32 pair -> packed fp16 hi + packed fp16 lo (x -> low half, y -> high half)
__device__ __forceinline__ uint32_t split2h(float2 v, uint32_t& lo) {
    __half2 h2 = __floats2half2_rn(v.x, v.y);
    float2 hf = __half22float2(h2);
    __half2 l2 = __floats2half2_rn(v.x - hf.x, v.y - hf.y);
    lo = *reinterpret_cast<uint32_t*>(&l2);
    return *reinterpret_cast<uint32_t*>(&h2);
}

// ---------- prep: fp16((features @ W)^T) -> g_b1 (2 threads per row) ----------
__global__ void feat_w_kernel(const float* __restrict__ feat,
                              const float* __restrict__ W) {
    __shared__ float sW[F_DIM * F_DIM];
    int tid = threadIdx.x;
    for (int i = tid; i < F_DIM * F_DIM; i += 128) sW[i] = W[i];
    __syncthreads();
    int g = blockIdx.x * 128 + tid;
    int row = g >> 1;
    int c0  = (g & 1) * 16;
    float f[F_DIM];
    const float4* fr = reinterpret_cast<const float4*>(feat + (size_t)row * F_DIM);
#pragma unroll
    for (int i = 0; i < 8; i++) {
        float4 v = fr[i];
        f[4*i] = v.x; f[4*i+1] = v.y; f[4*i+2] = v.z; f[4*i+3] = v.w;
    }
#pragma unroll 4
    for (int cc = 0; cc < 16; cc++) {
        int c = c0 + cc;
        float acc = 0.f;
#pragma unroll
        for (int k = 0; k < F_DIM; k++) acc = fmaf(f[k], sW[k * F_DIM + c], acc);
        g_b1[(size_t)c * N_DIM + row] = __float2half_rn(acc);
    }
}

// ---------- persistent big GEMM: fp16 2-pass (A split, B single) ----------
template <int MODE>
__global__ __launch_bounds__(THREADS, 1)
void big_gemm_mma(const float* __restrict__ A) {
    const __half* __restrict__ B = (MODE == 1) ? g_b1 : g_b2;

    extern __shared__ char smem[];
    const uint32_t sb = smem_u32(smem);
    const int tid  = threadIdx.x;
    const int lane = tid & 31;
    const int w    = tid >> 5;

    const int u0 = (blockIdx.x * TOTAL_UNITS) / GRID;
    const int u1 = ((blockIdx.x + 1) * TOTAL_UNITS) / GRID;
    const int S0 = u0 * UNIT_STAGES;
    const int S1 = u1 * UNIT_STAGES;

    // ---- producer slots ----
    int arow[8]; int agr[8]; uint32_t adst[8];
#pragma unroll
    for (int i = 0; i < 8; i++) {
        int chunk = tid + THREADS * i;
        arow[i] = chunk >> 3;  agr[i] = chunk & 7;
        adst[i] = (uint32_t)(arow[i] * 128 + ((agr[i] ^ (arow[i] & 7)) << 4));
    }
    // B: 32 rows x 4 granules(16B) = 128 chunks -> threads 0..127 only
    const int bn = tid >> 2, bg = tid & 3;
    const __half* bsrc = B + (size_t)bn * N_DIM + bg * 8;
    const uint32_t bdst = (uint32_t)(STAGE_A_SZ + bn * ROWB + bg * 16);

    auto issue = [&](int s) {
        const int u = s >> 5;
        const int m = u >> 4;
        const int kf = ((u & 15) * UNIT_STAGES + (s & 31)) * BK;
        const uint32_t stg = sb + (uint32_t)(s % NSTAGE) * STAGE_SZ;
        const float* abase = A + (size_t)(m * BM) * N_DIM + kf;
#pragma unroll
        for (int i = 0; i < 8; i++)
            CP_ASYNC16(stg + adst[i], abase + (size_t)arow[i] * N_DIM + agr[i] * 4);
        if (tid < 128) CP_ASYNC16(stg + bdst, bsrc + kf);
    };

    // ---- consumer addressing ----
    const int rA = w * 32 + (lane >> 2);
    const uint32_t xr = (uint32_t)(rA & 7);
    const uint32_t ar0 = (uint32_t)(rA * 128);
    const uint32_t gb  = (uint32_t)((lane & 3) >> 1);
    const uint32_t aib = (uint32_t)((lane & 1) * 8);
    const uint32_t boff = (uint32_t)(STAGE_A_SZ + (lane >> 2) * ROWB + (lane & 3) * 4);

    float acc[2][4][4];
#pragma unroll
    for (int t = 0; t < 2; t++)
#pragma unroll
        for (int j = 0; j < 4; j++)
#pragma unroll
            for (int i = 0; i < 4; i++) acc[t][j][i] = 0.f;

    issue(S0);     CP_COMMIT();
    issue(S0 + 1); CP_COMMIT();
    issue(S0 + 2); CP_COMMIT();
    issue(S0 + 3); CP_COMMIT();

    for (int s = S0; s < S1; s++) {
        CP_WAIT3();
        __syncthreads();
        if (s + 4 < S1) issue(s + 4);
        CP_COMMIT();

        const uint32_t stg = sb + (uint32_t)(s % NSTAGE) * STAGE_SZ;
#pragma unroll
        for (int kk = 0; kk < 2; kk++) {
            const uint32_t g0 = (gb + (uint32_t)(kk * 4)) ^ xr;
            const uint32_t g2 = (gb + (uint32_t)(kk * 4) + 2) ^ xr;
            uint32_t ah[2][4], al[2][4];
#pragma unroll
            for (int t = 0; t < 2; t++) {
                const uint32_t r0b = stg + ar0 + (uint32_t)(t * 16 * 128);
                float2 v0 = lds_f2(r0b + (g0 << 4) + aib);
                float2 v1 = lds_f2(r0b + 8 * 128 + (g0 << 4) + aib);
                float2 v2 = lds_f2(r0b + (g2 << 4) + aib);
                float2 v3 = lds_f2(r0b + 8 * 128 + (g2 << 4) + aib);
                ah[t][0] = split2h(v0, al[t][0]);
                ah[t][1] = split2h(v1, al[t][1]);
                ah[t][2] = split2h(v2, al[t][2]);
                ah[t][3] = split2h(v3, al[t][3]);
            }
            const uint32_t bH = stg + boff + (uint32_t)(kk * 32);
#pragma unroll
            for (int j = 0; j < 4; j++) {
                const uint32_t bo = bH + (uint32_t)(j * 8 * ROWB);
                uint32_t b0 = lds32(bo);
                uint32_t b1 = lds32(bo + 16);
#pragma unroll
                for (int t = 0; t < 2; t++) {
                    mma_f16(acc[t][j], ah[t], b0, b1);   // Ah * B
                    mma_f16(acc[t][j], al[t], b0, b1);   // Al * B
                }
            }
        }

        if ((s & 31) == 31) {
            const int u = s >> 5;
            const int m = u >> 4, kc = u & 15;
            float* pp = g_part + ((size_t)kc << 19);
#pragma unroll
            for (int t = 0; t < 2; t++) {
                const int gr0 = m * BM + w * 32 + t * 16 + (lane >> 2);
                const int gr1 = gr0 + 8;
#pragma unroll
                for (int j = 0; j < 4; j++) {
                    const int c = j * 8 + (lane & 3) * 2;
                    *reinterpret_cast<float2*>(pp + (size_t)gr0 * F_DIM + c) =
                        make_float2(acc[t][j][0], acc[t][j][1]);
                    *reinterpret_cast<float2*>(pp + (size_t)gr1 * F_DIM + c) =
                        make_float2(acc[t][j][2], acc[t][j][3]);
                    acc[t][j][0] = acc[t][j][1] = acc[t][j][2] = acc[t][j][3] = 0.f;
                }
            }
        }
    }
}

// ---------- reduce partials -> diag scale -> fp16 -> g_b2 (transposed) ----------
__global__ void reduce_split_kernel(const float* __restrict__ diag) {
    __shared__ unsigned short sh[F_DIM][33];
    const int tid = threadIdx.x;
    const int r0 = blockIdx.x * 32;
    const int rl = tid >> 3;
    const int c4 = (tid & 7) * 4;
    const int r = r0 + rl;
    float4 acc = *reinterpret_cast<const float4*>(g_part + (size_t)r * F_DIM + c4);
#pragma unroll
    for (int kc = 1; kc < KCHUNKS; kc++) {
        float4 v = *reinterpret_cast<const float4*>(
            g_part + ((size_t)kc << 19) + (size_t)r * F_DIM + c4);
        acc.x += v.x; acc.y += v.y; acc.z += v.z; acc.w += v.w;
    }
    const float d = diag[r];
    float vv[4] = {acc.x * d, acc.y * d, acc.z * d, acc.w * d};
#pragma unroll
    for (int i = 0; i < 4; i++) {
        __half h = __float2half_rn(vv[i]);
        sh[c4 + i][rl] = *reinterpret_cast<unsigned short*>(&h);
    }
    __syncthreads();
    const int cc = tid >> 3;
    const int rr = (tid & 7) * 4;
    ushort4 oh = make_ushort4(sh[cc][rr], sh[cc][rr+1], sh[cc][rr+2], sh[cc][rr+3]);
    *reinterpret_cast<ushort4*>(&g_b2[(size_t)cc * N_DIM + r0 + rr]) = oh;
}

// ---------- reduce partials -> f32 out ----------
__global__ void reduce_out_kernel(float* __restrict__ out) {
    const int idx = blockIdx.x * blockDim.x + threadIdx.x;
    float4 acc = *reinterpret_cast<const float4*>(g_part + (size_t)idx * 4);
#pragma unroll
    for (int kc = 1; kc < KCHUNKS; kc++) {
        float4 v = *reinterpret_cast<const float4*>(
            g_part + ((size_t)kc << 19) + (size_t)idx * 4);
        acc.x += v.x; acc.y += v.y; acc.z += v.z; acc.w += v.w;
    }
    *reinterpret_cast<float4*>(out + (size_t)idx * 4) = acc;
}

extern "C" void kernel_launch(void* const* d_in, const int* in_sizes, int n_in,
                              void* d_out, int out_size) {
    const float* feat = (const float*)d_in[0];  // [16384, 32]
    const float* wav  = (const float*)d_in[1];  // [16384, 16384]
    const float* wavi = (const float*)d_in[2];  // [16384, 16384]
    const float* diag = (const float*)d_in[3];  // [16384]
    const float* Wm   = (const float*)d_in[4];  // [32, 32]
    float* out = (float*)d_out;

    cudaFuncSetAttribute(big_gemm_mma<1>, cudaFuncAttributeMaxDynamicSharedMemorySize, SMEM_TOTAL);
    cudaFuncSetAttribute(big_gemm_mma<2>, cudaFuncAttributeMaxDynamicSharedMemorySize, SMEM_TOTAL);

    feat_w_kernel<<<N_DIM * 2 / 128, 128>>>(feat, Wm);
    big_gemm_mma<1><<<GRID, THREADS, SMEM_TOTAL>>>(wavi);
    reduce_split_kernel<<<N_DIM / 32, 256>>>(diag);
    big_gemm_mma<2><<<GRID, THREADS, SMEM_TOTAL>>>(wav);
    reduce_out_kernel<<<(N_DIM * F_DIM / 4) / 256, 256>>>(out);
}

// round 11
// speedup vs baseline: 1.0783x; 1.0243x over previous
#include <cuda_runtime.h>
#include <cuda_fp16.h>
#include <cstdint>

#define N_DIM   16384
#define F_DIM   32
#define BM      256
#define BK      32
#define THREADS 256
#define GRID    148
#define KCHUNKS 16
#define UNIT_STAGES 32
#define TOTAL_UNITS (64 * KCHUNKS)         // 1024 units; 512 stages per m-tile
#define ROWB    80

// ---- smem stage layout ----
#define STAGE_A_SZ 32768                   // 256 rows x 32 f32 (128B/row, swizzled)
#define BH_SZ      2560                    // 32 rows x 80B (single fp16 B)
#define STAGE_SZ   (STAGE_A_SZ + BH_SZ)    // 35328
#define NSTAGE     6
#define SMEM_TOTAL (NSTAGE * STAGE_SZ)     // 211968 (1 CTA/SM)

__device__ __align__(16) __half g_b1[F_DIM * N_DIM];
__device__ __align__(16) __half g_b2[F_DIM * N_DIM];
// per-CTA flush slots: [cta][0..1][256 rows][32 cols] f32  (9.7 MB)
__device__ __align__(16) float g_part[GRID * 2 * BM * F_DIM];

// ---------------- helpers ----------------
__device__ __forceinline__ uint32_t smem_u32(const void* p) {
    uint32_t a;
    asm("{ .reg .u64 t; cvta.to.shared.u64 t, %1; cvt.u32.u64 %0, t; }" : "=r"(a) : "l"(p));
    return a;
}
#define CP_ASYNC16(dst, src) \
    asm volatile("cp.async.cg.shared.global [%0], [%1], 16;" :: "r"(dst), "l"(src) : "memory")
#define CP_COMMIT()  asm volatile("cp.async.commit_group;" ::: "memory")
#define CP_WAIT4()   asm volatile("cp.async.wait_group 4;" ::: "memory")

__device__ __forceinline__ float2 lds_f2(uint32_t a) {
    float2 v;
    asm volatile("ld.shared.v2.f32 {%0,%1}, [%2];" : "=f"(v.x), "=f"(v.y) : "r"(a));
    return v;
}
__device__ __forceinline__ uint32_t lds32(uint32_t addr) {
    uint32_t v;
    asm volatile("ld.shared.b32 %0, [%1];" : "=r"(v) : "r"(addr));
    return v;
}
__device__ __forceinline__ void mma_f16(float* c, const uint32_t* a, uint32_t b0, uint32_t b1) {
    asm volatile("mma.sync.aligned.m16n8k16.row.col.f32.f16.f16.f32 "
                 "{%0,%1,%2,%3}, {%4,%5,%6,%7}, {%8,%9}, {%0,%1,%2,%3};"
                 : "+f"(c[0]), "+f"(c[1]), "+f"(c[2]), "+f"(c[3])
                 : "r"(a[0]), "r"(a[1]), "r"(a[2]), "r"(a[3]), "r"(b0), "r"(b1));
}
__device__ __forceinline__ uint32_t split2h(float2 v, uint32_t& lo) {
    __half2 h2 = __floats2half2_rn(v.x, v.y);
    float2 hf = __half22float2(h2);
    __half2 l2 = __floats2half2_rn(v.x - hf.x, v.y - hf.y);
    lo = *reinterpret_cast<uint32_t*>(&l2);
    return *reinterpret_cast<uint32_t*>(&h2);
}

// unit ownership math: u0(b) = floor(b*1024/148) = floor(b*256/37)
__device__ __forceinline__ int unit_start(int b) { return (b << 8) / 37; }
__device__ __forceinline__ int cta_of_unit(int u) { return (37 * u + 36) >> 8; }

// slot-sum for rows of m-tile m: sum over owning CTAs' flush buffers
__device__ __forceinline__ float4 sum_slots(int m, int lr, int c4) {
    const int bf = cta_of_unit(16 * m);
    const int bl = cta_of_unit(16 * m + 15);
    float4 acc = make_float4(0.f, 0.f, 0.f, 0.f);
    for (int b = bf; b <= bl; b++) {
        const int idx = m - (unit_start(b) >> 4);
        const float4 v = *reinterpret_cast<const float4*>(
            g_part + (((size_t)(b * 2 + idx)) << 13) + lr * F_DIM + c4);
        acc.x += v.x; acc.y += v.y; acc.z += v.z; acc.w += v.w;
    }
    return acc;
}

// ---------- prep: fp16((features @ W)^T) -> g_b1 ----------
__global__ void feat_w_kernel(const float* __restrict__ feat,
                              const float* __restrict__ W) {
    __shared__ float sW[F_DIM * F_DIM];
    int tid = threadIdx.x;
    for (int i = tid; i < F_DIM * F_DIM; i += 128) sW[i] = W[i];
    __syncthreads();
    int g = blockIdx.x * 128 + tid;
    int row = g >> 1;
    int c0  = (g & 1) * 16;
    float f[F_DIM];
    const float4* fr = reinterpret_cast<const float4*>(feat + (size_t)row * F_DIM);
#pragma unroll
    for (int i = 0; i < 8; i++) {
        float4 v = fr[i];
        f[4*i] = v.x; f[4*i+1] = v.y; f[4*i+2] = v.z; f[4*i+3] = v.w;
    }
#pragma unroll 4
    for (int cc = 0; cc < 16; cc++) {
        int c = c0 + cc;
        float acc = 0.f;
#pragma unroll
        for (int k = 0; k < F_DIM; k++) acc = fmaf(f[k], sW[k * F_DIM + c], acc);
        g_b1[(size_t)c * N_DIM + row] = __float2half_rn(acc);
    }
}

// ---------- persistent big GEMM: fp16 2-pass, continuous k accumulation ----------
template <int MODE>
__global__ __launch_bounds__(THREADS, 1)
void big_gemm_mma(const float* __restrict__ A) {
    const __half* __restrict__ B = (MODE == 1) ? g_b1 : g_b2;

    extern __shared__ char smem[];
    const uint32_t sb = smem_u32(smem);
    const int tid  = threadIdx.x;
    const int lane = tid & 31;
    const int w    = tid >> 5;

    const int u0 = unit_start(blockIdx.x);
    const int u1 = unit_start(blockIdx.x + 1);
    const int S0 = u0 * UNIT_STAGES;
    const int S1 = u1 * UNIT_STAGES;

    // ---- producer slots ----
    int arow[8]; int agr[8]; uint32_t adst[8];
#pragma unroll
    for (int i = 0; i < 8; i++) {
        int chunk = tid + THREADS * i;
        arow[i] = chunk >> 3;  agr[i] = chunk & 7;
        adst[i] = (uint32_t)(arow[i] * 128 + ((agr[i] ^ (arow[i] & 7)) << 4));
    }
    const int bn = tid >> 2, bg = tid & 3;
    const __half* bsrc = B + (size_t)bn * N_DIM + bg * 8;
    const uint32_t bdst = (uint32_t)(STAGE_A_SZ + bn * ROWB + bg * 16);

    auto issue = [&](int s) {
        const int u = s >> 5;
        const int m = u >> 4;
        const int kf = ((u & 15) * UNIT_STAGES + (s & 31)) * BK;
        const uint32_t stg = sb + (uint32_t)(s % NSTAGE) * STAGE_SZ;
        const float* abase = A + (size_t)(m * BM) * N_DIM + kf;
#pragma unroll
        for (int i = 0; i < 8; i++)
            CP_ASYNC16(stg + adst[i], abase + (size_t)arow[i] * N_DIM + agr[i] * 4);
        if (tid < 128) CP_ASYNC16(stg + bdst, bsrc + kf);
    };

    // ---- consumer addressing ----
    const int rA = w * 32 + (lane >> 2);
    const uint32_t xr = (uint32_t)(rA & 7);
    const uint32_t ar0 = (uint32_t)(rA * 128);
    const uint32_t gb  = (uint32_t)((lane & 3) >> 1);
    const uint32_t aib = (uint32_t)((lane & 1) * 8);
    const uint32_t boff = (uint32_t)(STAGE_A_SZ + (lane >> 2) * ROWB + (lane & 3) * 4);

    float acc[2][4][4];
#pragma unroll
    for (int t = 0; t < 2; t++)
#pragma unroll
        for (int j = 0; j < 4; j++)
#pragma unroll
            for (int i = 0; i < 4; i++) acc[t][j][i] = 0.f;

    issue(S0);     CP_COMMIT();
    issue(S0 + 1); CP_COMMIT();
    issue(S0 + 2); CP_COMMIT();
    issue(S0 + 3); CP_COMMIT();
    issue(S0 + 4); CP_COMMIT();

    for (int s = S0; s < S1; s++) {
        CP_WAIT4();
        __syncthreads();
        if (s + 5 < S1) issue(s + 5);
        CP_COMMIT();

        const uint32_t stg = sb + (uint32_t)(s % NSTAGE) * STAGE_SZ;
#pragma unroll
        for (int kk = 0; kk < 2; kk++) {
            const uint32_t g0 = (gb + (uint32_t)(kk * 4)) ^ xr;
            const uint32_t g2 = (gb + (uint32_t)(kk * 4) + 2) ^ xr;
            uint32_t ah[2][4], al[2][4];
#pragma unroll
            for (int t = 0; t < 2; t++) {
                const uint32_t r0b = stg + ar0 + (uint32_t)(t * 16 * 128);
                float2 v0 = lds_f2(r0b + (g0 << 4) + aib);
                float2 v1 = lds_f2(r0b + 8 * 128 + (g0 << 4) + aib);
                float2 v2 = lds_f2(r0b + (g2 << 4) + aib);
                float2 v3 = lds_f2(r0b + 8 * 128 + (g2 << 4) + aib);
                ah[t][0] = split2h(v0, al[t][0]);
                ah[t][1] = split2h(v1, al[t][1]);
                ah[t][2] = split2h(v2, al[t][2]);
                ah[t][3] = split2h(v3, al[t][3]);
            }
            const uint32_t bH = stg + boff + (uint32_t)(kk * 32);
#pragma unroll
            for (int j = 0; j < 4; j++) {
                const uint32_t bo = bH + (uint32_t)(j * 8 * ROWB);
                uint32_t b0 = lds32(bo);
                uint32_t b1 = lds32(bo + 16);
#pragma unroll
                for (int t = 0; t < 2; t++) {
                    mma_f16(acc[t][j], ah[t], b0, b1);
                    mma_f16(acc[t][j], al[t], b0, b1);
                }
            }
        }

        // flush only when m-tile finishes for this CTA (every 512 stages) or range end
        if (((s + 1) & 511) == 0 || s + 1 == S1) {
            const int idx = (s >> 9) - (S0 >> 9);          // 0 or 1
            float* pp = g_part + (((size_t)(blockIdx.x * 2 + idx)) << 13);
#pragma unroll
            for (int t = 0; t < 2; t++) {
                const int lr0 = w * 32 + t * 16 + (lane >> 2);   // local row in m-tile
                const int lr1 = lr0 + 8;
#pragma unroll
                for (int j = 0; j < 4; j++) {
                    const int c = j * 8 + (lane & 3) * 2;
                    *reinterpret_cast<float2*>(pp + (size_t)lr0 * F_DIM + c) =
                        make_float2(acc[t][j][0], acc[t][j][1]);
                    *reinterpret_cast<float2*>(pp + (size_t)lr1 * F_DIM + c) =
                        make_float2(acc[t][j][2], acc[t][j][3]);
                    acc[t][j][0] = acc[t][j][1] = acc[t][j][2] = acc[t][j][3] = 0.f;
                }
            }
        }
    }
}

// ---------- reduce slots -> diag scale -> fp16 -> g_b2 (transposed) ----------
__global__ void reduce_split_kernel(const float* __restrict__ diag) {
    __shared__ unsigned short sh[F_DIM][33];
    const int tid = threadIdx.x;
    const int r0 = blockIdx.x * 32;                 // 32 global rows per block
    const int m  = r0 >> 8;                         // m-tile (BM=256)
    const int rl = tid >> 3;                        // 0..31
    const int c4 = (tid & 7) * 4;
    const int lr = (r0 & 255) + rl;                 // local row within m-tile
    float4 acc = sum_slots(m, lr, c4);
    const float d = diag[r0 + rl];
    float vv[4] = {acc.x * d, acc.y * d, acc.z * d, acc.w * d};
#pragma unroll
    for (int i = 0; i < 4; i++) {
        __half h = __float2half_rn(vv[i]);
        sh[c4 + i][rl] = *reinterpret_cast<unsigned short*>(&h);
    }
    __syncthreads();
    const int cc = tid >> 3;
    const int rr = (tid & 7) * 4;
    ushort4 oh = make_ushort4(sh[cc][rr], sh[cc][rr+1], sh[cc][rr+2], sh[cc][rr+3]);
    *reinterpret_cast<ushort4*>(&g_b2[(size_t)cc * N_DIM + r0 + rr]) = oh;
}

// ---------- reduce slots -> f32 out ----------
__global__ void reduce_out_kernel(float* __restrict__ out) {
    const int tid = threadIdx.x;
    const int r0 = blockIdx.x * 32;
    const int m  = r0 >> 8;
    const int rl = tid >> 3;
    const int c4 = (tid & 7) * 4;
    const int lr = (r0 & 255) + rl;
    float4 acc = sum_slots(m, lr, c4);
    *reinterpret_cast<float4*>(out + (size_t)(r0 + rl) * F_DIM + c4) = acc;
}

extern "C" void kernel_launch(void* const* d_in, const int* in_sizes, int n_in,
                              void* d_out, int out_size) {
    const float* feat = (const float*)d_in[0];  // [16384, 32]
    const float* wav  = (const float*)d_in[1];  // [16384, 16384]
    const float* wavi = (const float*)d_in[2];  // [16384, 16384]
    const float* diag = (const float*)d_in[3];  // [16384]
    const float* Wm   = (const float*)d_in[4];  // [32, 32]
    float* out = (float*)d_out;

    cudaFuncSetAttribute(big_gemm_mma<1>, cudaFuncAttributeMaxDynamicSharedMemorySize, SMEM_TOTAL);
    cudaFuncSetAttribute(big_gemm_mma<2>, cudaFuncAttributeMaxDynamicSharedMemorySize, SMEM_TOTAL);

    feat_w_kernel<<<N_DIM * 2 / 128, 128>>>(feat, Wm);
    big_gemm_mma<1><<<GRID, THREADS, SMEM_TOTAL>>>(wavi);
    reduce_split_kernel<<<N_DIM / 32, 256>>>(diag);
    big_gemm_mma<2><<<GRID, THREADS, SMEM_TOTAL>>>(wav);
    reduce_out_kernel<<<N_DIM / 32, 256>>>(out);
}

// round 12
// speedup vs baseline: 1.2091x; 1.1213x over previous
#include <cuda_runtime.h>
#include <cuda_fp16.h>
#include <cstdint>

#define N_DIM   16384
#define F_DIM   32
#define BM      256
#define BK      32
#define THREADS 256
#define GRID    148
#define UNIT_STAGES 32
#define TOTAL_UNITS 1024                   // 64 m-tiles x 16 k-chunks
#define ROWB    80

// ---- smem stage layout ----
#define STAGE_A_SZ 32768                   // 256 rows x 32 f32 (128B/row, swizzled)
#define BH_SZ      2560                    // 32 rows x 80B (single fp16 B)
#define STAGE_SZ   (STAGE_A_SZ + BH_SZ)    // 35328
#define NSTAGE     6
#define SMEM_TOTAL (NSTAGE * STAGE_SZ)     // 211968 (1 CTA/SM)

__device__ __align__(16) __half g_b1[F_DIM * N_DIM];
__device__ __align__(16) __half g_b2[F_DIM * N_DIM];
// per-CTA flush slots: [cta][0..1][256 rows][32 cols] f32
__device__ __align__(16) float g_part[GRID * 2 * BM * F_DIM];

// ---------------- helpers ----------------
__device__ __forceinline__ uint32_t smem_u32(const void* p) {
    uint32_t a;
    asm("{ .reg .u64 t; cvta.to.shared.u64 t, %1; cvt.u32.u64 %0, t; }" : "=r"(a) : "l"(p));
    return a;
}
// A loads: 256B L2 prefetch (next stage's 128B becomes an L2 hit)
#define CP_ASYNC16_PF(dst, src) \
    asm volatile("cp.async.cg.shared.global.L2::256B [%0], [%1], 16;" :: "r"(dst), "l"(src) : "memory")
#define CP_ASYNC16(dst, src) \
    asm volatile("cp.async.cg.shared.global [%0], [%1], 16;" :: "r"(dst), "l"(src) : "memory")
#define CP_COMMIT()  asm volatile("cp.async.commit_group;" ::: "memory")
#define CP_WAIT4()   asm volatile("cp.async.wait_group 4;" ::: "memory")

__device__ __forceinline__ float2 lds_f2(uint32_t a) {
    float2 v;
    asm volatile("ld.shared.v2.f32 {%0,%1}, [%2];" : "=f"(v.x), "=f"(v.y) : "r"(a));
    return v;
}
__device__ __forceinline__ uint32_t lds32(uint32_t addr) {
    uint32_t v;
    asm volatile("ld.shared.b32 %0, [%1];" : "=r"(v) : "r"(addr));
    return v;
}
__device__ __forceinline__ void mma_f16(float* c, const uint32_t* a, uint32_t b0, uint32_t b1) {
    asm volatile("mma.sync.aligned.m16n8k16.row.col.f32.f16.f16.f32 "
                 "{%0,%1,%2,%3}, {%4,%5,%6,%7}, {%8,%9}, {%0,%1,%2,%3};"
                 : "+f"(c[0]), "+f"(c[1]), "+f"(c[2]), "+f"(c[3])
                 : "r"(a[0]), "r"(a[1]), "r"(a[2]), "r"(a[3]), "r"(b0), "r"(b1));
}
__device__ __forceinline__ uint32_t split2h(float2 v, uint32_t& lo) {
    __half2 h2 = __floats2half2_rn(v.x, v.y);
    float2 hf = __half22float2(h2);
    __half2 l2 = __floats2half2_rn(v.x - hf.x, v.y - hf.y);
    lo = *reinterpret_cast<uint32_t*>(&l2);
    return *reinterpret_cast<uint32_t*>(&h2);
}

// unit ownership math: u0(b) = floor(b*1024/148) = floor(b*256/37)
__device__ __forceinline__ int unit_start(int b) { return (b << 8) / 37; }
__device__ __forceinline__ int cta_of_unit(int u) { return (37 * u + 36) >> 8; }

__device__ __forceinline__ float4 sum_slots(int m, int lr, int c4) {
    const int bf = cta_of_unit(16 * m);
    const int bl = cta_of_unit(16 * m + 15);
    float4 acc = make_float4(0.f, 0.f, 0.f, 0.f);
    for (int b = bf; b <= bl; b++) {
        const int idx = m - (unit_start(b) >> 4);
        const float4 v = *reinterpret_cast<const float4*>(
            g_part + (((size_t)(b * 2 + idx)) << 13) + lr * F_DIM + c4);
        acc.x += v.x; acc.y += v.y; acc.z += v.z; acc.w += v.w;
    }
    return acc;
}

// ---------- prep: fp16((features @ W)^T) -> g_b1 ----------
__global__ void feat_w_kernel(const float* __restrict__ feat,
                              const float* __restrict__ W) {
    __shared__ float sW[F_DIM * F_DIM];
    int tid = threadIdx.x;
    for (int i = tid; i < F_DIM * F_DIM; i += 128) sW[i] = W[i];
    __syncthreads();
    int g = blockIdx.x * 128 + tid;
    int row = g >> 1;
    int c0  = (g & 1) * 16;
    float f[F_DIM];
    const float4* fr = reinterpret_cast<const float4*>(feat + (size_t)row * F_DIM);
#pragma unroll
    for (int i = 0; i < 8; i++) {
        float4 v = fr[i];
        f[4*i] = v.x; f[4*i+1] = v.y; f[4*i+2] = v.z; f[4*i+3] = v.w;
    }
#pragma unroll 4
    for (int cc = 0; cc < 16; cc++) {
        int c = c0 + cc;
        float acc = 0.f;
#pragma unroll
        for (int k = 0; k < F_DIM; k++) acc = fmaf(f[k], sW[k * F_DIM + c], acc);
        g_b1[(size_t)c * N_DIM + row] = __float2half_rn(acc);
    }
}

// ---------- persistent big GEMM: fp16 2-pass, continuous k accumulation ----------
template <int MODE>
__global__ __launch_bounds__(THREADS, 1)
void big_gemm_mma(const float* __restrict__ A) {
    const __half* __restrict__ B = (MODE == 1) ? g_b1 : g_b2;

    extern __shared__ char smem[];
    const uint32_t sb = smem_u32(smem);
    const int tid  = threadIdx.x;
    const int lane = tid & 31;
    const int w    = tid >> 5;

    const int u0 = unit_start(blockIdx.x);
    const int u1 = unit_start(blockIdx.x + 1);
    const int S0 = u0 * UNIT_STAGES;
    const int S1 = u1 * UNIT_STAGES;

    // ---- producer slots ----
    int arow[8]; int agr[8]; uint32_t adst[8];
#pragma unroll
    for (int i = 0; i < 8; i++) {
        int chunk = tid + THREADS * i;
        arow[i] = chunk >> 3;  agr[i] = chunk & 7;
        adst[i] = (uint32_t)(arow[i] * 128 + ((agr[i] ^ (arow[i] & 7)) << 4));
    }
    const int bn = tid >> 2, bg = tid & 3;
    const __half* bsrc = B + (size_t)bn * N_DIM + bg * 8;
    const uint32_t bdst = (uint32_t)(STAGE_A_SZ + bn * ROWB + bg * 16);

    auto issue = [&](int s) {
        const int u = s >> 5;
        const int m = u >> 4;
        const int kf = ((u & 15) * UNIT_STAGES + (s & 31)) * BK;
        const uint32_t stg = sb + (uint32_t)(s % NSTAGE) * STAGE_SZ;
        const float* abase = A + (size_t)(m * BM) * N_DIM + kf;
#pragma unroll
        for (int i = 0; i < 8; i++)
            CP_ASYNC16_PF(stg + adst[i], abase + (size_t)arow[i] * N_DIM + agr[i] * 4);
        if (tid < 128) CP_ASYNC16(stg + bdst, bsrc + kf);
    };

    // ---- consumer addressing ----
    const int rA = w * 32 + (lane >> 2);
    const uint32_t xr = (uint32_t)(rA & 7);
    const uint32_t ar0 = (uint32_t)(rA * 128);
    const uint32_t gb  = (uint32_t)((lane & 3) >> 1);
    const uint32_t aib = (uint32_t)((lane & 1) * 8);
    const uint32_t boff = (uint32_t)(STAGE_A_SZ + (lane >> 2) * ROWB + (lane & 3) * 4);

    float acc[2][4][4];
#pragma unroll
    for (int t = 0; t < 2; t++)
#pragma unroll
        for (int j = 0; j < 4; j++)
#pragma unroll
            for (int i = 0; i < 4; i++) acc[t][j][i] = 0.f;

    issue(S0);     CP_COMMIT();
    issue(S0 + 1); CP_COMMIT();
    issue(S0 + 2); CP_COMMIT();
    issue(S0 + 3); CP_COMMIT();
    issue(S0 + 4); CP_COMMIT();

    for (int s = S0; s < S1; s++) {
        CP_WAIT4();
        __syncthreads();
        if (s + 5 < S1) issue(s + 5);
        CP_COMMIT();

        const uint32_t stg = sb + (uint32_t)(s % NSTAGE) * STAGE_SZ;
#pragma unroll
        for (int kk = 0; kk < 2; kk++) {
            const uint32_t g0 = (gb + (uint32_t)(kk * 4)) ^ xr;
            const uint32_t g2 = (gb + (uint32_t)(kk * 4) + 2) ^ xr;
            uint32_t ah[2][4], al[2][4];
#pragma unroll
            for (int t = 0; t < 2; t++) {
                const uint32_t r0b = stg + ar0 + (uint32_t)(t * 16 * 128);
                float2 v0 = lds_f2(r0b + (g0 << 4) + aib);
                float2 v1 = lds_f2(r0b + 8 * 128 + (g0 << 4) + aib);
                float2 v2 = lds_f2(r0b + (g2 << 4) + aib);
                float2 v3 = lds_f2(r0b + 8 * 128 + (g2 << 4) + aib);
                ah[t][0] = split2h(v0, al[t][0]);
                ah[t][1] = split2h(v1, al[t][1]);
                ah[t][2] = split2h(v2, al[t][2]);
                ah[t][3] = split2h(v3, al[t][3]);
            }
            const uint32_t bH = stg + boff + (uint32_t)(kk * 32);
#pragma unroll
            for (int j = 0; j < 4; j++) {
                const uint32_t bo = bH + (uint32_t)(j * 8 * ROWB);
                uint32_t b0 = lds32(bo);
                uint32_t b1 = lds32(bo + 16);
#pragma unroll
                for (int t = 0; t < 2; t++) {
                    mma_f16(acc[t][j], ah[t], b0, b1);
                    mma_f16(acc[t][j], al[t], b0, b1);
                }
            }
        }

        if (((s + 1) & 511) == 0 || s + 1 == S1) {
            const int idx = (s >> 9) - (S0 >> 9);
            float* pp = g_part + (((size_t)(blockIdx.x * 2 + idx)) << 13);
#pragma unroll
            for (int t = 0; t < 2; t++) {
                const int lr0 = w * 32 + t * 16 + (lane >> 2);
                const int lr1 = lr0 + 8;
#pragma unroll
                for (int j = 0; j < 4; j++) {
                    const int c = j * 8 + (lane & 3) * 2;
                    *reinterpret_cast<float2*>(pp + (size_t)lr0 * F_DIM + c) =
                        make_float2(acc[t][j][0], acc[t][j][1]);
                    *reinterpret_cast<float2*>(pp + (size_t)lr1 * F_DIM + c) =
                        make_float2(acc[t][j][2], acc[t][j][3]);
                    acc[t][j][0] = acc[t][j][1] = acc[t][j][2] = acc[t][j][3] = 0.f;
                }
            }
        }
    }
}

// ---------- reduce slots -> diag scale -> fp16 -> g_b2 (transposed) ----------
__global__ void reduce_split_kernel(const float* __restrict__ diag) {
    __shared__ unsigned short sh[F_DIM][33];
    const int tid = threadIdx.x;
    const int r0 = blockIdx.x * 32;
    const int m  = r0 >> 8;
    const int rl = tid >> 3;
    const int c4 = (tid & 7) * 4;
    const int lr = (r0 & 255) + rl;
    float4 acc = sum_slots(m, lr, c4);
    const float d = diag[r0 + rl];
    float vv[4] = {acc.x * d, acc.y * d, acc.z * d, acc.w * d};
#pragma unroll
    for (int i = 0; i < 4; i++) {
        __half h = __float2half_rn(vv[i]);
        sh[c4 + i][rl] = *reinterpret_cast<unsigned short*>(&h);
    }
    __syncthreads();
    const int cc = tid >> 3;
    const int rr = (tid & 7) * 4;
    ushort4 oh = make_ushort4(sh[cc][rr], sh[cc][rr+1], sh[cc][rr+2], sh[cc][rr+3]);
    *reinterpret_cast<ushort4*>(&g_b2[(size_t)cc * N_DIM + r0 + rr]) = oh;
}

// ---------- reduce slots -> f32 out ----------
__global__ void reduce_out_kernel(float* __restrict__ out) {
    const int tid = threadIdx.x;
    const int r0 = blockIdx.x * 32;
    const int m  = r0 >> 8;
    const int rl = tid >> 3;
    const int c4 = (tid & 7) * 4;
    const int lr = (r0 & 255) + rl;
    float4 acc = sum_slots(m, lr, c4);
    *reinterpret_cast<float4*>(out + (size_t)(r0 + rl) * F_DIM + c4) = acc;
}

extern "C" void kernel_launch(void* const* d_in, const int* in_sizes, int n_in,
                              void* d_out, int out_size) {
    const float* feat = (const float*)d_in[0];  // [16384, 32]
    const float* wav  = (const float*)d_in[1];  // [16384, 16384]
    const float* wavi = (const float*)d_in[2];  // [16384, 16384]
    const float* diag = (const float*)d_in[3];  // [16384]
    const float* Wm   = (const float*)d_in[4];  // [32, 32]
    float* out = (float*)d_out;

    cudaFuncSetAttribute(big_gemm_mma<1>, cudaFuncAttributeMaxDynamicSharedMemorySize, SMEM_TOTAL);
    cudaFuncSetAttribute(big_gemm_mma<2>, cudaFuncAttributeMaxDynamicSharedMemorySize, SMEM_TOTAL);

    feat_w_kernel<<<N_DIM * 2 / 128, 128>>>(feat, Wm);
    big_gemm_mma<1><<<GRID, THREADS, SMEM_TOTAL>>>(wavi);
    reduce_split_kernel<<<N_DIM / 32, 256>>>(diag);
    big_gemm_mma<2><<<GRID, THREADS, SMEM_TOTAL>>>(wav);
    reduce_out_kernel<<<N_DIM / 32, 256>>>(out);
}

// round 14
// speedup vs baseline: 1.2229x; 1.0115x over previous
#include <cuda_runtime.h>
#include <cuda_fp16.h>
#include <cstdint>

#define N_DIM   16384
#define F_DIM   32
#define BM      256
#define BK      32
#define THREADS 256
#define GRID    148
#define UNIT_STAGES 32
#define TOTAL_UNITS 1024                   // 64 m-tiles x 16 k-chunks

// ---- per-warp smem stage layout ----
#define WA_SZ    4096                      // 32 rows x 128B (swizzled)
#define ROWB     80
#define WB_OFF   WA_SZ
#define WB_SZ    (32 * ROWB)               // 2560
#define WSTAGE   (WA_SZ + WB_SZ)           // 6656
#define NSTAGE   4
#define WARP_SMEM (NSTAGE * WSTAGE)        // 26624
#define SMEM_TOTAL (8 * WARP_SMEM)         // 212992 (1 CTA/SM)

__device__ __align__(16) __half g_b1[F_DIM * N_DIM];
__device__ __align__(16) __half g_b2[F_DIM * N_DIM];
// per-CTA flush slots: [cta][0..1][256 rows][32 cols] f32
__device__ __align__(16) float g_part[GRID * 2 * BM * F_DIM];

// ---------------- helpers ----------------
__device__ __forceinline__ uint32_t smem_u32(const void* p) {
    uint32_t a;
    asm("{ .reg .u64 t; cvta.to.shared.u64 t, %1; cvt.u32.u64 %0, t; }" : "=r"(a) : "l"(p));
    return a;
}
#define CP_ASYNC16_PF(dst, src) \
    asm volatile("cp.async.cg.shared.global.L2::256B [%0], [%1], 16;" :: "r"(dst), "l"(src) : "memory")
#define CP_ASYNC16(dst, src) \
    asm volatile("cp.async.cg.shared.global [%0], [%1], 16;" :: "r"(dst), "l"(src) : "memory")
#define CP_COMMIT()  asm volatile("cp.async.commit_group;" ::: "memory")
#define CP_WAIT2()   asm volatile("cp.async.wait_group 2;" ::: "memory")

__device__ __forceinline__ float2 lds_f2(uint32_t a) {
    float2 v;
    asm volatile("ld.shared.v2.f32 {%0,%1}, [%2];" : "=f"(v.x), "=f"(v.y) : "r"(a));
    return v;
}
__device__ __forceinline__ uint32_t lds32(uint32_t addr) {
    uint32_t v;
    asm volatile("ld.shared.b32 %0, [%1];" : "=r"(v) : "r"(addr));
    return v;
}
__device__ __forceinline__ void mma_f16(float* c, const uint32_t* a, uint32_t b0, uint32_t b1) {
    asm volatile("mma.sync.aligned.m16n8k16.row.col.f32.f16.f16.f32 "
                 "{%0,%1,%2,%3}, {%4,%5,%6,%7}, {%8,%9}, {%0,%1,%2,%3};"
                 : "+f"(c[0]), "+f"(c[1]), "+f"(c[2]), "+f"(c[3])
                 : "r"(a[0]), "r"(a[1]), "r"(a[2]), "r"(a[3]), "r"(b0), "r"(b1));
}
__device__ __forceinline__ uint32_t split2h(float2 v, uint32_t& lo) {
    __half2 h2 = __floats2half2_rn(v.x, v.y);
    float2 hf = __half22float2(h2);
    __half2 l2 = __floats2half2_rn(v.x - hf.x, v.y - hf.y);
    lo = *reinterpret_cast<uint32_t*>(&l2);
    return *reinterpret_cast<uint32_t*>(&h2);
}

// unit ownership math: u0(b) = floor(b*1024/148) = floor(b*256/37)
__device__ __forceinline__ int unit_start(int b) { return (b << 8) / 37; }
__device__ __forceinline__ int cta_of_unit(int u) { return (37 * u + 36) >> 8; }

__device__ __forceinline__ float4 sum_slots(int m, int lr, int c4) {
    const int bf = cta_of_unit(16 * m);
    const int bl = cta_of_unit(16 * m + 15);
    float4 acc = make_float4(0.f, 0.f, 0.f, 0.f);
    for (int b = bf; b <= bl; b++) {
        const int idx = m - (unit_start(b) >> 4);
        const float4 v = *reinterpret_cast<const float4*>(
            g_part + (((size_t)(b * 2 + idx)) << 13) + lr * F_DIM + c4);
        acc.x += v.x; acc.y += v.y; acc.z += v.z; acc.w += v.w;
    }
    return acc;
}

// ---------- prep: fp16((features @ W)^T) -> g_b1 ----------
__global__ void feat_w_kernel(const float* __restrict__ feat,
                              const float* __restrict__ W) {
    __shared__ float sW[F_DIM * F_DIM];
    int tid = threadIdx.x;
    for (int i = tid; i < F_DIM * F_DIM; i += 128) sW[i] = W[i];
    __syncthreads();
    int g = blockIdx.x * 128 + tid;
    int row = g >> 1;
    int c0  = (g & 1) * 16;
    float f[F_DIM];
    const float4* fr = reinterpret_cast<const float4*>(feat + (size_t)row * F_DIM);
#pragma unroll
    for (int i = 0; i < 8; i++) {
        float4 v = fr[i];
        f[4*i] = v.x; f[4*i+1] = v.y; f[4*i+2] = v.z; f[4*i+3] = v.w;
    }
#pragma unroll 4
    for (int cc = 0; cc < 16; cc++) {
        int c = c0 + cc;
        float acc = 0.f;
#pragma unroll
        for (int k = 0; k < F_DIM; k++) acc = fmaf(f[k], sW[k * F_DIM + c], acc);
        g_b1[(size_t)c * N_DIM + row] = __float2half_rn(acc);
    }
}

// ---------- persistent big GEMM: per-warp self-paced pipelines ----------
template <int MODE>
__global__ __launch_bounds__(THREADS, 1)
void big_gemm_mma(const float* __restrict__ A) {
    const __half* __restrict__ B = (MODE == 1) ? g_b1 : g_b2;

    extern __shared__ char smem[];
    const int tid  = threadIdx.x;
    const int lane = tid & 31;
    const int w    = tid >> 5;
    const uint32_t wb = smem_u32(smem) + (uint32_t)(w * WARP_SMEM);

    const int u0 = unit_start(blockIdx.x);
    const int u1 = unit_start(blockIdx.x + 1);
    const int S0 = u0 * UNIT_STAGES;
    const int S1 = u1 * UNIT_STAGES;

    // ---- producer slots (warp-local) ----
    int alr[8]; int agr[8]; uint32_t adst[8];
#pragma unroll
    for (int i = 0; i < 8; i++) {
        int chunk = lane + 32 * i;
        alr[i] = chunk >> 3;  agr[i] = chunk & 7;
        adst[i] = (uint32_t)(alr[i] * 128 + ((agr[i] ^ (alr[i] & 7)) << 4));
    }
    int bn[4]; int bgr[4]; uint32_t bdst[4];
#pragma unroll
    for (int j = 0; j < 4; j++) {
        int chunk = lane + 32 * j;
        bn[j] = chunk >> 2;  bgr[j] = chunk & 3;
        bdst[j] = (uint32_t)(WB_OFF + bn[j] * ROWB + bgr[j] * 16);
    }

    // NOTE: no commit inside — caller commits unconditionally every iteration
    auto issue = [&](int s) {
        const int u = s >> 5;
        const int m = u >> 4;
        const int kf = ((u & 15) * UNIT_STAGES + (s & 31)) * BK;
        const uint32_t stg = wb + (uint32_t)(s & 3) * WSTAGE;
        const float* abase = A + (size_t)(m * BM + w * 32) * N_DIM + kf;
#pragma unroll
        for (int i = 0; i < 8; i++)
            CP_ASYNC16_PF(stg + adst[i], abase + (size_t)alr[i] * N_DIM + agr[i] * 4);
#pragma unroll
        for (int j = 0; j < 4; j++)
            CP_ASYNC16(stg + bdst[j], B + (size_t)bn[j] * N_DIM + kf + bgr[j] * 8);
    };

    // ---- consumer addressing (warp-local rows) ----
    const uint32_t xr  = (uint32_t)(lane >> 2);
    const uint32_t ar0 = (uint32_t)((lane >> 2) * 128);
    const uint32_t gb  = (uint32_t)((lane & 3) >> 1);
    const uint32_t aib = (uint32_t)((lane & 1) * 8);
    const uint32_t boff = (uint32_t)(WB_OFF + (lane >> 2) * ROWB + (lane & 3) * 4);

    float acc[2][4][4];
#pragma unroll
    for (int t = 0; t < 2; t++)
#pragma unroll
        for (int j = 0; j < 4; j++)
#pragma unroll
            for (int i = 0; i < 4; i++) acc[t][j][i] = 0.f;

    issue(S0);     CP_COMMIT();
    issue(S0 + 1); CP_COMMIT();
    issue(S0 + 2); CP_COMMIT();

    for (int s = S0; s < S1; s++) {
        CP_WAIT2();
        __syncwarp();
        if (s + 3 < S1) issue(s + 3);
        CP_COMMIT();   // unconditional: empty group keeps wait_group count aligned

        const uint32_t stg = wb + (uint32_t)(s & 3) * WSTAGE;
#pragma unroll
        for (int kk = 0; kk < 2; kk++) {
            const uint32_t g0 = (gb + (uint32_t)(kk * 4)) ^ xr;
            const uint32_t g2 = (gb + (uint32_t)(kk * 4) + 2) ^ xr;
            uint32_t ah[2][4], al[2][4];
#pragma unroll
            for (int t = 0; t < 2; t++) {
                const uint32_t r0b = stg + ar0 + (uint32_t)(t * 16 * 128);
                float2 v0 = lds_f2(r0b + (g0 << 4) + aib);
                float2 v1 = lds_f2(r0b + 8 * 128 + (g0 << 4) + aib);
                float2 v2 = lds_f2(r0b + (g2 << 4) + aib);
                float2 v3 = lds_f2(r0b + 8 * 128 + (g2 << 4) + aib);
                ah[t][0] = split2h(v0, al[t][0]);
                ah[t][1] = split2h(v1, al[t][1]);
                ah[t][2] = split2h(v2, al[t][2]);
                ah[t][3] = split2h(v3, al[t][3]);
            }
            const uint32_t bH = stg + boff + (uint32_t)(kk * 32);
#pragma unroll
            for (int j = 0; j < 4; j++) {
                const uint32_t bo = bH + (uint32_t)(j * 8 * ROWB);
                uint32_t b0 = lds32(bo);
                uint32_t b1 = lds32(bo + 16);
#pragma unroll
                for (int t = 0; t < 2; t++) {
                    mma_f16(acc[t][j], ah[t], b0, b1);
                    mma_f16(acc[t][j], al[t], b0, b1);
                }
            }
        }

        if (((s + 1) & 511) == 0 || s + 1 == S1) {
            const int idx = (s >> 9) - (S0 >> 9);
            float* pp = g_part + (((size_t)(blockIdx.x * 2 + idx)) << 13);
#pragma unroll
            for (int t = 0; t < 2; t++) {
                const int lr0 = w * 32 + t * 16 + (lane >> 2);
                const int lr1 = lr0 + 8;
#pragma unroll
                for (int j = 0; j < 4; j++) {
                    const int c = j * 8 + (lane & 3) * 2;
                    *reinterpret_cast<float2*>(pp + (size_t)lr0 * F_DIM + c) =
                        make_float2(acc[t][j][0], acc[t][j][1]);
                    *reinterpret_cast<float2*>(pp + (size_t)lr1 * F_DIM + c) =
                        make_float2(acc[t][j][2], acc[t][j][3]);
                    acc[t][j][0] = acc[t][j][1] = acc[t][j][2] = acc[t][j][3] = 0.f;
                }
            }
        }
    }
}

// ---------- reduce slots -> diag scale -> fp16 -> g_b2 (transposed) ----------
__global__ void reduce_split_kernel(const float* __restrict__ diag) {
    __shared__ unsigned short sh[F_DIM][33];
    const int tid = threadIdx.x;
    const int r0 = blockIdx.x * 32;
    const int m  = r0 >> 8;
    const int rl = tid >> 3;
    const int c4 = (tid & 7) * 4;
    const int lr = (r0 & 255) + rl;
    float4 acc = sum_slots(m, lr, c4);
    const float d = diag[r0 + rl];
    float vv[4] = {acc.x * d, acc.y * d, acc.z * d, acc.w * d};
#pragma unroll
    for (int i = 0; i < 4; i++) {
        __half h = __float2half_rn(vv[i]);
        sh[c4 + i][rl] = *reinterpret_cast<unsigned short*>(&h);
    }
    __syncthreads();
    const int cc = tid >> 3;
    const int rr = (tid & 7) * 4;
    ushort4 oh = make_ushort4(sh[cc][rr], sh[cc][rr+1], sh[cc][rr+2], sh[cc][rr+3]);
    *reinterpret_cast<ushort4*>(&g_b2[(size_t)cc * N_DIM + r0 + rr]) = oh;
}

// ---------- reduce slots -> f32 out ----------
__global__ void reduce_out_kernel(float* __restrict__ out) {
    const int tid = threadIdx.x;
    const int r0 = blockIdx.x * 32;
    const int m  = r0 >> 8;
    const int rl = tid >> 3;
    const int c4 = (tid & 7) * 4;
    const int lr = (r0 & 255) + rl;
    float4 acc = sum_slots(m, lr, c4);
    *reinterpret_cast<float4*>(out + (size_t)(r0 + rl) * F_DIM + c4) = acc;
}

extern "C" void kernel_launch(void* const* d_in, const int* in_sizes, int n_in,
                              void* d_out, int out_size) {
    const float* feat = (const float*)d_in[0];  // [16384, 32]
    const float* wav  = (const float*)d_in[1];  // [16384, 16384]
    const float* wavi = (const float*)d_in[2];  // [16384, 16384]
    const float* diag = (const float*)d_in[3];  // [16384]
    const float* Wm   = (const float*)d_in[4];  // [32, 32]
    float* out = (float*)d_out;

    cudaFuncSetAttribute(big_gemm_mma<1>, cudaFuncAttributeMaxDynamicSharedMemorySize, SMEM_TOTAL);
    cudaFuncSetAttribute(big_gemm_mma<2>, cudaFuncAttributeMaxDynamicSharedMemorySize, SMEM_TOTAL);

    feat_w_kernel<<<N_DIM * 2 / 128, 128>>>(feat, Wm);
    big_gemm_mma<1><<<GRID, THREADS, SMEM_TOTAL>>>(wavi);
    reduce_split_kernel<<<N_DIM / 32, 256>>>(diag);
    big_gemm_mma<2><<<GRID, THREADS, SMEM_TOTAL>>>(wav);
    reduce_out_kernel<<<N_DIM / 32, 256>>>(out);
}